// round 2
// baseline (speedup 1.0000x reference)
#include <cuda_runtime.h>
#include <cstdint>

#define D 64
#define MAX_NODES 50000
#define MAX_EDGES 800000

// Scratch (no allocations allowed)
__device__ __align__(256) float g_h0[MAX_NODES * D];
__device__ __align__(256) float g_h1[MAX_NODES * D];
__device__ __align__(256) float g_colsum[D];
__device__ int g_deg[MAX_NODES];
__device__ int g_off[MAX_NODES + 1];
__device__ int g_cursor[MAX_NODES];
__device__ int g_srcs[MAX_EDGES];   // src ids grouped by dst (CSR)

// ---------------------------------------------------------------------------
// CSR build
// ---------------------------------------------------------------------------
__global__ void zero_deg_kernel(int* deg, int n) {
    int i = blockIdx.x * blockDim.x + threadIdx.x;
    if (i < n) deg[i] = 0;
}

__global__ void hist_kernel(const int* __restrict__ dst, int* __restrict__ deg,
                            int n_edges) {
    int e = blockIdx.x * blockDim.x + threadIdx.x;
    if (e < n_edges) atomicAdd(&deg[dst[e]], 1);
}

// Single-block exclusive scan over n counters -> off[0..n], and cursor = off.
__global__ __launch_bounds__(1024)
void scan_kernel(const int* __restrict__ deg, int* __restrict__ off,
                 int* __restrict__ cursor, int n) {
    __shared__ int part[1024];
    int tid = threadIdx.x;
    int chunk = (n + 1023) / 1024;
    int b = tid * chunk;
    int s = 0;
    for (int k = 0; k < chunk; k++) {
        int idx = b + k;
        if (idx < n) s += deg[idx];
    }
    part[tid] = s;
    __syncthreads();
    // Hillis-Steele inclusive scan
    for (int d = 1; d < 1024; d <<= 1) {
        int v = (tid >= d) ? part[tid - d] : 0;
        __syncthreads();
        part[tid] += v;
        __syncthreads();
    }
    int run = (tid > 0) ? part[tid - 1] : 0;  // exclusive prefix
    for (int k = 0; k < chunk; k++) {
        int idx = b + k;
        if (idx < n) {
            off[idx] = run;
            cursor[idx] = run;
            run += deg[idx];
        }
    }
    if (tid == 1023) off[n] = part[1023];
}

__global__ void csr_scatter_kernel(const int* __restrict__ src,
                                   const int* __restrict__ dst,
                                   int* __restrict__ cursor,
                                   int* __restrict__ srcs, int n_edges) {
    int e = blockIdx.x * blockDim.x + threadIdx.x;
    if (e >= n_edges) return;
    int d = dst[e];
    int pos = atomicAdd(&cursor[d], 1);
    srcs[pos] = src[e];
}

// ---------------------------------------------------------------------------
// Fused gather + MLP:
//   r[node] = h[node] + sum_{e: dst=node} h[src[e]]
//   out[node] = relu(r @ Wa + ba) @ Wb + bb
// Block = 256 threads = 8 warps; warp owns 4 nodes; lane owns 2 columns.
// ---------------------------------------------------------------------------
__global__ __launch_bounds__(256)
void gather_mlp_kernel(const float* __restrict__ h, float* __restrict__ out,
                       const int* __restrict__ off, const int* __restrict__ srcs,
                       const float* __restrict__ Wa, const float* __restrict__ ba,
                       const float* __restrict__ Wb, const float* __restrict__ bb,
                       int n_rows) {
    __shared__ float sWa[D * D];
    __shared__ float sWb[D * D];
    __shared__ float sba[D];
    __shared__ float sbb[D];
    __shared__ float sbuf[8][4][D];

    int tid = threadIdx.x;
    for (int i = tid; i < D * D; i += 256) { sWa[i] = Wa[i]; sWb[i] = Wb[i]; }
    if (tid < D) { sba[tid] = ba[tid]; sbb[tid] = bb[tid]; }
    __syncthreads();

    int warp = tid >> 5;
    int lane = tid & 31;
    int rowbase = (blockIdx.x * 8 + warp) * 4;
    if (rowbase >= n_rows) return;
    int c = lane * 2;

    // Gather-sum each of this warp's 4 nodes into sbuf
    #pragma unroll
    for (int j = 0; j < 4; j++) {
        int node = rowbase + j;
        float2 acc;
        if (node < n_rows) {
            acc = *reinterpret_cast<const float2*>(h + (size_t)node * D + c);
            int beg = __ldg(off + node);
            int end = __ldg(off + node + 1);
            int i = beg;
            for (; i + 1 < end; i += 2) {
                int s0 = __ldg(srcs + i);
                int s1 = __ldg(srcs + i + 1);
                float2 v0 = *reinterpret_cast<const float2*>(h + (size_t)s0 * D + c);
                float2 v1 = *reinterpret_cast<const float2*>(h + (size_t)s1 * D + c);
                acc.x += v0.x + v1.x;
                acc.y += v0.y + v1.y;
            }
            if (i < end) {
                int s0 = __ldg(srcs + i);
                float2 v0 = *reinterpret_cast<const float2*>(h + (size_t)s0 * D + c);
                acc.x += v0.x;
                acc.y += v0.y;
            }
        } else {
            acc = make_float2(0.f, 0.f);
        }
        *reinterpret_cast<float2*>(&sbuf[warp][j][c]) = acc;
    }
    __syncwarp();

    // Stage 1: t = relu(r @ Wa + ba)
    float2 acc[4];
    {
        float2 bia = *reinterpret_cast<const float2*>(&sba[c]);
        #pragma unroll
        for (int j = 0; j < 4; j++) acc[j] = bia;
        #pragma unroll 8
        for (int k = 0; k < D; k++) {
            float2 w = *reinterpret_cast<const float2*>(&sWa[k * D + c]);
            #pragma unroll
            for (int j = 0; j < 4; j++) {
                float rv = sbuf[warp][j][k];
                acc[j].x = fmaf(rv, w.x, acc[j].x);
                acc[j].y = fmaf(rv, w.y, acc[j].y);
            }
        }
    }
    __syncwarp();
    #pragma unroll
    for (int j = 0; j < 4; j++) {
        sbuf[warp][j][c]     = fmaxf(acc[j].x, 0.f);
        sbuf[warp][j][c + 1] = fmaxf(acc[j].y, 0.f);
    }
    __syncwarp();

    // Stage 2: out = t @ Wb + bb
    {
        float2 bib = *reinterpret_cast<const float2*>(&sbb[c]);
        #pragma unroll
        for (int j = 0; j < 4; j++) acc[j] = bib;
        #pragma unroll 8
        for (int k = 0; k < D; k++) {
            float2 w = *reinterpret_cast<const float2*>(&sWb[k * D + c]);
            #pragma unroll
            for (int j = 0; j < 4; j++) {
                float rv = sbuf[warp][j][k];
                acc[j].x = fmaf(rv, w.x, acc[j].x);
                acc[j].y = fmaf(rv, w.y, acc[j].y);
            }
        }
    }
    int nr = min(4, n_rows - rowbase);
    for (int j = 0; j < nr; j++) {
        *reinterpret_cast<float2*>(out + (size_t)(rowbase + j) * D + c) = acc[j];
    }
}

// ---------------------------------------------------------------------------
// Mean pooling + output head
// ---------------------------------------------------------------------------
__global__ void zero_colsum_kernel(float* p) {
    if (threadIdx.x < D) p[threadIdx.x] = 0.f;
}

__global__ void reduce_cols_kernel(const float* __restrict__ h,
                                   float* __restrict__ colsum, int n_rows) {
    __shared__ float s[256];
    int col = threadIdx.x & 63;
    int rsub = threadIdx.x >> 6;
    float acc = 0.f;
    for (int row = blockIdx.x * 4 + rsub; row < n_rows; row += gridDim.x * 4)
        acc += h[(size_t)row * D + col];
    s[threadIdx.x] = acc;
    __syncthreads();
    if (threadIdx.x < 64) {
        float v = s[threadIdx.x] + s[threadIdx.x + 64] +
                  s[threadIdx.x + 128] + s[threadIdx.x + 192];
        atomicAdd(&colsum[threadIdx.x], v);
    }
}

__global__ void final_out_kernel(const float* __restrict__ colsum,
                                 const float* __restrict__ Wout,
                                 const float* __restrict__ bout,
                                 float* __restrict__ out, int n_rows) {
    int j = threadIdx.x;
    if (j >= 16) return;
    float inv = 1.0f / (float)n_rows;
    float acc = bout[j];
    #pragma unroll
    for (int k = 0; k < D; k++)
        acc = fmaf(colsum[k] * inv, Wout[k * 16 + j], acc);
    out[j] = acc;
}

// ---------------------------------------------------------------------------
// Launch
// ---------------------------------------------------------------------------
extern "C" void kernel_launch(void* const* d_in, const int* in_sizes, int n_in,
                              void* d_out, int out_size) {
    const float* features = (const float*)d_in[0];
    const int*   src      = (const int*)d_in[1];
    const int*   dst      = (const int*)d_in[2];
    const float* Wa[3] = {(const float*)d_in[3], (const float*)d_in[7],  (const float*)d_in[11]};
    const float* ba[3] = {(const float*)d_in[4], (const float*)d_in[8],  (const float*)d_in[12]};
    const float* Wb[3] = {(const float*)d_in[5], (const float*)d_in[9],  (const float*)d_in[13]};
    const float* bb[3] = {(const float*)d_in[6], (const float*)d_in[10], (const float*)d_in[14]};
    const float* Wout = (const float*)d_in[15];
    const float* bout = (const float*)d_in[16];
    float* out = (float*)d_out;

    int n_nodes = in_sizes[0] / D;
    int n_edges = in_sizes[1];

    float *h0, *h1, *colsum;
    int *deg, *off, *cursor, *srcs;
    cudaGetSymbolAddress((void**)&h0, g_h0);
    cudaGetSymbolAddress((void**)&h1, g_h1);
    cudaGetSymbolAddress((void**)&colsum, g_colsum);
    cudaGetSymbolAddress((void**)&deg, g_deg);
    cudaGetSymbolAddress((void**)&off, g_off);
    cudaGetSymbolAddress((void**)&cursor, g_cursor);
    cudaGetSymbolAddress((void**)&srcs, g_srcs);

    int node_blocks = (n_nodes + 255) / 256;
    int edge_blocks = (n_edges + 255) / 256;
    int mlp_blocks = (n_nodes + 31) / 32;

    // Build CSR (dst -> list of srcs)
    zero_deg_kernel<<<node_blocks, 256>>>(deg, n_nodes);
    hist_kernel<<<edge_blocks, 256>>>(dst, deg, n_edges);
    scan_kernel<<<1, 1024>>>(deg, off, cursor, n_nodes);
    csr_scatter_kernel<<<edge_blocks, 256>>>(src, dst, cursor, srcs, n_edges);

    // 3 GIN layers, fused gather+MLP
    gather_mlp_kernel<<<mlp_blocks, 256>>>(features, h0, off, srcs,
                                           Wa[0], ba[0], Wb[0], bb[0], n_nodes);
    gather_mlp_kernel<<<mlp_blocks, 256>>>(h0, h1, off, srcs,
                                           Wa[1], ba[1], Wb[1], bb[1], n_nodes);
    gather_mlp_kernel<<<mlp_blocks, 256>>>(h1, h0, off, srcs,
                                           Wa[2], ba[2], Wb[2], bb[2], n_nodes);

    // Mean pool + head
    zero_colsum_kernel<<<1, 64>>>(colsum);
    reduce_cols_kernel<<<256, 256>>>(h0, colsum, n_nodes);
    final_out_kernel<<<1, 32>>>(colsum, Wout, bout, out, n_nodes);
}

// round 3
// speedup vs baseline: 1.0010x; 1.0010x over previous
#include <cuda_runtime.h>
#include <cstdint>

#define D 64
#define MAX_NODES 50000
#define MAX_EDGES 800000

// Scratch (no allocations allowed)
__device__ __align__(256) float g_h0[MAX_NODES * D];
__device__ __align__(256) float g_h1[MAX_NODES * D];
__device__ __align__(256) float g_colsum[D];
__device__ int g_deg[MAX_NODES];
__device__ int g_off[MAX_NODES + 1];
__device__ int g_cursor[MAX_NODES];
__device__ int g_srcs[MAX_EDGES];   // src ids grouped by dst (CSR)

// ---------------------------------------------------------------------------
// CSR build
// ---------------------------------------------------------------------------
__global__ void zero_deg_kernel(int* deg, int n) {
    int i = blockIdx.x * blockDim.x + threadIdx.x;
    if (i < n) deg[i] = 0;
}

__global__ void hist_kernel(const int* __restrict__ dst, int* __restrict__ deg,
                            int n_edges) {
    int e = blockIdx.x * blockDim.x + threadIdx.x;
    if (e < n_edges) atomicAdd(&deg[dst[e]], 1);
}

// Single-block exclusive scan over n counters -> off[0..n], and cursor = off.
__global__ __launch_bounds__(1024)
void scan_kernel(const int* __restrict__ deg, int* __restrict__ off,
                 int* __restrict__ cursor, int n) {
    __shared__ int part[1024];
    int tid = threadIdx.x;
    int chunk = (n + 1023) / 1024;
    int b = tid * chunk;
    int s = 0;
    for (int k = 0; k < chunk; k++) {
        int idx = b + k;
        if (idx < n) s += deg[idx];
    }
    part[tid] = s;
    __syncthreads();
    // Hillis-Steele inclusive scan
    for (int d = 1; d < 1024; d <<= 1) {
        int v = (tid >= d) ? part[tid - d] : 0;
        __syncthreads();
        part[tid] += v;
        __syncthreads();
    }
    int run = (tid > 0) ? part[tid - 1] : 0;  // exclusive prefix
    for (int k = 0; k < chunk; k++) {
        int idx = b + k;
        if (idx < n) {
            off[idx] = run;
            cursor[idx] = run;
            run += deg[idx];
        }
    }
    if (tid == 1023) off[n] = part[1023];
}

__global__ void csr_scatter_kernel(const int* __restrict__ src,
                                   const int* __restrict__ dst,
                                   int* __restrict__ cursor,
                                   int* __restrict__ srcs, int n_edges) {
    int e = blockIdx.x * blockDim.x + threadIdx.x;
    if (e >= n_edges) return;
    int d = dst[e];
    int pos = atomicAdd(&cursor[d], 1);
    srcs[pos] = src[e];
}

// ---------------------------------------------------------------------------
// Fused gather + MLP:
//   r[node] = h[node] + sum_{e: dst=node} h[src[e]]
//   out[node] = relu(r @ Wa + ba) @ Wb + bb
// Block = 256 threads = 8 warps; warp owns 4 nodes; lane owns 2 columns.
// ---------------------------------------------------------------------------
__global__ __launch_bounds__(256)
void gather_mlp_kernel(const float* __restrict__ h, float* __restrict__ out,
                       const int* __restrict__ off, const int* __restrict__ srcs,
                       const float* __restrict__ Wa, const float* __restrict__ ba,
                       const float* __restrict__ Wb, const float* __restrict__ bb,
                       int n_rows) {
    __shared__ float sWa[D * D];
    __shared__ float sWb[D * D];
    __shared__ float sba[D];
    __shared__ float sbb[D];
    __shared__ float sbuf[8][4][D];

    int tid = threadIdx.x;
    for (int i = tid; i < D * D; i += 256) { sWa[i] = Wa[i]; sWb[i] = Wb[i]; }
    if (tid < D) { sba[tid] = ba[tid]; sbb[tid] = bb[tid]; }
    __syncthreads();

    int warp = tid >> 5;
    int lane = tid & 31;
    int rowbase = (blockIdx.x * 8 + warp) * 4;
    if (rowbase >= n_rows) return;
    int c = lane * 2;

    // Gather-sum each of this warp's 4 nodes into sbuf
    #pragma unroll
    for (int j = 0; j < 4; j++) {
        int node = rowbase + j;
        float2 acc;
        if (node < n_rows) {
            acc = *reinterpret_cast<const float2*>(h + (size_t)node * D + c);
            int beg = __ldg(off + node);
            int end = __ldg(off + node + 1);
            int i = beg;
            for (; i + 1 < end; i += 2) {
                int s0 = __ldg(srcs + i);
                int s1 = __ldg(srcs + i + 1);
                float2 v0 = *reinterpret_cast<const float2*>(h + (size_t)s0 * D + c);
                float2 v1 = *reinterpret_cast<const float2*>(h + (size_t)s1 * D + c);
                acc.x += v0.x + v1.x;
                acc.y += v0.y + v1.y;
            }
            if (i < end) {
                int s0 = __ldg(srcs + i);
                float2 v0 = *reinterpret_cast<const float2*>(h + (size_t)s0 * D + c);
                acc.x += v0.x;
                acc.y += v0.y;
            }
        } else {
            acc = make_float2(0.f, 0.f);
        }
        *reinterpret_cast<float2*>(&sbuf[warp][j][c]) = acc;
    }
    __syncwarp();

    // Stage 1: t = relu(r @ Wa + ba)
    float2 acc[4];
    {
        float2 bia = *reinterpret_cast<const float2*>(&sba[c]);
        #pragma unroll
        for (int j = 0; j < 4; j++) acc[j] = bia;
        #pragma unroll 8
        for (int k = 0; k < D; k++) {
            float2 w = *reinterpret_cast<const float2*>(&sWa[k * D + c]);
            #pragma unroll
            for (int j = 0; j < 4; j++) {
                float rv = sbuf[warp][j][k];
                acc[j].x = fmaf(rv, w.x, acc[j].x);
                acc[j].y = fmaf(rv, w.y, acc[j].y);
            }
        }
    }
    __syncwarp();
    #pragma unroll
    for (int j = 0; j < 4; j++) {
        sbuf[warp][j][c]     = fmaxf(acc[j].x, 0.f);
        sbuf[warp][j][c + 1] = fmaxf(acc[j].y, 0.f);
    }
    __syncwarp();

    // Stage 2: out = t @ Wb + bb
    {
        float2 bib = *reinterpret_cast<const float2*>(&sbb[c]);
        #pragma unroll
        for (int j = 0; j < 4; j++) acc[j] = bib;
        #pragma unroll 8
        for (int k = 0; k < D; k++) {
            float2 w = *reinterpret_cast<const float2*>(&sWb[k * D + c]);
            #pragma unroll
            for (int j = 0; j < 4; j++) {
                float rv = sbuf[warp][j][k];
                acc[j].x = fmaf(rv, w.x, acc[j].x);
                acc[j].y = fmaf(rv, w.y, acc[j].y);
            }
        }
    }
    int nr = min(4, n_rows - rowbase);
    for (int j = 0; j < nr; j++) {
        *reinterpret_cast<float2*>(out + (size_t)(rowbase + j) * D + c) = acc[j];
    }
}

// ---------------------------------------------------------------------------
// Mean pooling + output head
// ---------------------------------------------------------------------------
__global__ void zero_colsum_kernel(float* p) {
    if (threadIdx.x < D) p[threadIdx.x] = 0.f;
}

__global__ void reduce_cols_kernel(const float* __restrict__ h,
                                   float* __restrict__ colsum, int n_rows) {
    __shared__ float s[256];
    int col = threadIdx.x & 63;
    int rsub = threadIdx.x >> 6;
    float acc = 0.f;
    for (int row = blockIdx.x * 4 + rsub; row < n_rows; row += gridDim.x * 4)
        acc += h[(size_t)row * D + col];
    s[threadIdx.x] = acc;
    __syncthreads();
    if (threadIdx.x < 64) {
        float v = s[threadIdx.x] + s[threadIdx.x + 64] +
                  s[threadIdx.x + 128] + s[threadIdx.x + 192];
        atomicAdd(&colsum[threadIdx.x], v);
    }
}

__global__ void final_out_kernel(const float* __restrict__ colsum,
                                 const float* __restrict__ Wout,
                                 const float* __restrict__ bout,
                                 float* __restrict__ out, int n_rows) {
    int j = threadIdx.x;
    if (j >= 16) return;
    float inv = 1.0f / (float)n_rows;
    float acc = bout[j];
    #pragma unroll
    for (int k = 0; k < D; k++)
        acc = fmaf(colsum[k] * inv, Wout[k * 16 + j], acc);
    out[j] = acc;
}

// ---------------------------------------------------------------------------
// Launch
// ---------------------------------------------------------------------------
extern "C" void kernel_launch(void* const* d_in, const int* in_sizes, int n_in,
                              void* d_out, int out_size) {
    const float* features = (const float*)d_in[0];
    const int*   src      = (const int*)d_in[1];
    const int*   dst      = (const int*)d_in[2];
    const float* Wa[3] = {(const float*)d_in[3], (const float*)d_in[7],  (const float*)d_in[11]};
    const float* ba[3] = {(const float*)d_in[4], (const float*)d_in[8],  (const float*)d_in[12]};
    const float* Wb[3] = {(const float*)d_in[5], (const float*)d_in[9],  (const float*)d_in[13]};
    const float* bb[3] = {(const float*)d_in[6], (const float*)d_in[10], (const float*)d_in[14]};
    const float* Wout = (const float*)d_in[15];
    const float* bout = (const float*)d_in[16];
    float* out = (float*)d_out;

    int n_nodes = in_sizes[0] / D;
    int n_edges = in_sizes[1];

    float *h0, *h1, *colsum;
    int *deg, *off, *cursor, *srcs;
    cudaGetSymbolAddress((void**)&h0, g_h0);
    cudaGetSymbolAddress((void**)&h1, g_h1);
    cudaGetSymbolAddress((void**)&colsum, g_colsum);
    cudaGetSymbolAddress((void**)&deg, g_deg);
    cudaGetSymbolAddress((void**)&off, g_off);
    cudaGetSymbolAddress((void**)&cursor, g_cursor);
    cudaGetSymbolAddress((void**)&srcs, g_srcs);

    int node_blocks = (n_nodes + 255) / 256;
    int edge_blocks = (n_edges + 255) / 256;
    int mlp_blocks = (n_nodes + 31) / 32;

    // Build CSR (dst -> list of srcs)
    zero_deg_kernel<<<node_blocks, 256>>>(deg, n_nodes);
    hist_kernel<<<edge_blocks, 256>>>(dst, deg, n_edges);
    scan_kernel<<<1, 1024>>>(deg, off, cursor, n_nodes);
    csr_scatter_kernel<<<edge_blocks, 256>>>(src, dst, cursor, srcs, n_edges);

    // 3 GIN layers, fused gather+MLP
    gather_mlp_kernel<<<mlp_blocks, 256>>>(features, h0, off, srcs,
                                           Wa[0], ba[0], Wb[0], bb[0], n_nodes);
    gather_mlp_kernel<<<mlp_blocks, 256>>>(h0, h1, off, srcs,
                                           Wa[1], ba[1], Wb[1], bb[1], n_nodes);
    gather_mlp_kernel<<<mlp_blocks, 256>>>(h1, h0, off, srcs,
                                           Wa[2], ba[2], Wb[2], bb[2], n_nodes);

    // Mean pool + head
    zero_colsum_kernel<<<1, 64>>>(colsum);
    reduce_cols_kernel<<<256, 256>>>(h0, colsum, n_nodes);
    final_out_kernel<<<1, 32>>>(colsum, Wout, bout, out, n_nodes);
}

// round 4
// speedup vs baseline: 1.1766x; 1.1755x over previous
#include <cuda_runtime.h>
#include <cuda_bf16.h>
#include <cstdint>

#define D 64
#define MAX_NODES 50000
#define MAX_EDGES 800000

// Scratch (no allocations allowed)
__device__ __align__(256) float g_h0[MAX_NODES * D];
__device__ __align__(256) float g_h1[MAX_NODES * D];
__device__ __align__(256) float g_agg[MAX_NODES * D];
__device__ __align__(256) __nv_bfloat16 g_hb[MAX_NODES * D];
__device__ __align__(256) float g_colsum[D];
__device__ int g_deg[MAX_NODES];
__device__ int g_off[MAX_NODES + 1];
__device__ int g_cursor[MAX_NODES];
__device__ int g_srcs[MAX_EDGES];   // src ids grouped by dst (CSR)

// ---------------------------------------------------------------------------
// CSR build
// ---------------------------------------------------------------------------
__global__ void zero_deg_kernel(int* deg, int n) {
    int i = blockIdx.x * blockDim.x + threadIdx.x;
    if (i < n) deg[i] = 0;
}

__global__ void hist_kernel(const int* __restrict__ dst, int* __restrict__ deg,
                            int n_edges) {
    int e = blockIdx.x * blockDim.x + threadIdx.x;
    if (e < n_edges) atomicAdd(&deg[dst[e]], 1);
}

__global__ __launch_bounds__(1024)
void scan_kernel(const int* __restrict__ deg, int* __restrict__ off,
                 int* __restrict__ cursor, int n) {
    __shared__ int part[1024];
    int tid = threadIdx.x;
    int chunk = (n + 1023) / 1024;
    int b = tid * chunk;
    int s = 0;
    for (int k = 0; k < chunk; k++) {
        int idx = b + k;
        if (idx < n) s += deg[idx];
    }
    part[tid] = s;
    __syncthreads();
    for (int d = 1; d < 1024; d <<= 1) {
        int v = (tid >= d) ? part[tid - d] : 0;
        __syncthreads();
        part[tid] += v;
        __syncthreads();
    }
    int run = (tid > 0) ? part[tid - 1] : 0;
    for (int k = 0; k < chunk; k++) {
        int idx = b + k;
        if (idx < n) {
            off[idx] = run;
            cursor[idx] = run;
            run += deg[idx];
        }
    }
    if (tid == 1023) off[n] = part[1023];
}

__global__ void csr_scatter_kernel(const int* __restrict__ src,
                                   const int* __restrict__ dst,
                                   int* __restrict__ cursor,
                                   int* __restrict__ srcs, int n_edges) {
    int e = blockIdx.x * blockDim.x + threadIdx.x;
    if (e >= n_edges) return;
    int d = dst[e];
    int pos = atomicAdd(&cursor[d], 1);
    srcs[pos] = src[e];
}

// ---------------------------------------------------------------------------
// features (f32) -> bf16 copy
// ---------------------------------------------------------------------------
__global__ void cvt_bf16_kernel(const float2* __restrict__ in,
                                __nv_bfloat162* __restrict__ out, int n2) {
    int i = blockIdx.x * blockDim.x + threadIdx.x;
    if (i < n2) out[i] = __float22bfloat162_rn(in[i]);
}

// ---------------------------------------------------------------------------
// Gather: agg[node] = h_f32[node] + sum_{e: dst=node} h_bf16[src[e]]
// Thread = (node, chunk c in 0..7): 8 threads per node, 8 columns each.
// Neighbor rows read as bf16 (128B/row, one cache line per node-group).
// Unrolled x4 -> 4 independent 16B loads in flight per thread.
// ---------------------------------------------------------------------------
__device__ __forceinline__ void acc_add8(float acc[8], uint4 u) {
    float2 f0 = __bfloat1622float2(*reinterpret_cast<__nv_bfloat162*>(&u.x));
    float2 f1 = __bfloat1622float2(*reinterpret_cast<__nv_bfloat162*>(&u.y));
    float2 f2 = __bfloat1622float2(*reinterpret_cast<__nv_bfloat162*>(&u.z));
    float2 f3 = __bfloat1622float2(*reinterpret_cast<__nv_bfloat162*>(&u.w));
    acc[0] += f0.x; acc[1] += f0.y; acc[2] += f1.x; acc[3] += f1.y;
    acc[4] += f2.x; acc[5] += f2.y; acc[6] += f3.x; acc[7] += f3.y;
}

__global__ __launch_bounds__(256)
void gather_kernel(const float* __restrict__ hf,
                   const __nv_bfloat16* __restrict__ hb,
                   float* __restrict__ agg,
                   const int* __restrict__ off, const int* __restrict__ srcs,
                   int n_nodes) {
    int tid = blockIdx.x * blockDim.x + threadIdx.x;
    int node = tid >> 3;
    int c = tid & 7;
    if (node >= n_nodes) return;

    float acc[8];
    {
        const float4* hp = reinterpret_cast<const float4*>(hf + (size_t)node * D + c * 8);
        float4 a0 = hp[0], a1 = hp[1];
        acc[0] = a0.x; acc[1] = a0.y; acc[2] = a0.z; acc[3] = a0.w;
        acc[4] = a1.x; acc[5] = a1.y; acc[6] = a1.z; acc[7] = a1.w;
    }

    int beg = __ldg(off + node);
    int end = __ldg(off + node + 1);
    int i = beg;
    for (; i + 4 <= end; i += 4) {
        int s0 = __ldg(srcs + i);
        int s1 = __ldg(srcs + i + 1);
        int s2 = __ldg(srcs + i + 2);
        int s3 = __ldg(srcs + i + 3);
        uint4 u0 = *reinterpret_cast<const uint4*>(hb + (size_t)s0 * D + c * 8);
        uint4 u1 = *reinterpret_cast<const uint4*>(hb + (size_t)s1 * D + c * 8);
        uint4 u2 = *reinterpret_cast<const uint4*>(hb + (size_t)s2 * D + c * 8);
        uint4 u3 = *reinterpret_cast<const uint4*>(hb + (size_t)s3 * D + c * 8);
        acc_add8(acc, u0);
        acc_add8(acc, u1);
        acc_add8(acc, u2);
        acc_add8(acc, u3);
    }
    for (; i < end; i++) {
        int s0 = __ldg(srcs + i);
        uint4 u0 = *reinterpret_cast<const uint4*>(hb + (size_t)s0 * D + c * 8);
        acc_add8(acc, u0);
    }

    float4* op = reinterpret_cast<float4*>(agg + (size_t)node * D + c * 8);
    op[0] = make_float4(acc[0], acc[1], acc[2], acc[3]);
    op[1] = make_float4(acc[4], acc[5], acc[6], acc[7]);
}

// ---------------------------------------------------------------------------
// Fused MLP: out = relu(r @ Wa + ba) @ Wb + bb ; also emits bf16 copy of out.
// Block = 256 threads = 8 warps; warp owns 4 rows; lane owns 2 columns.
// ---------------------------------------------------------------------------
__global__ __launch_bounds__(256)
void mlp_kernel(const float* __restrict__ r, float* __restrict__ out,
                __nv_bfloat16* __restrict__ out_bf,
                const float* __restrict__ Wa, const float* __restrict__ ba,
                const float* __restrict__ Wb, const float* __restrict__ bb,
                int n_rows) {
    __shared__ float sWa[D * D];
    __shared__ float sWb[D * D];
    __shared__ float sba[D];
    __shared__ float sbb[D];
    __shared__ float sbuf[8][4][D];

    int tid = threadIdx.x;
    for (int i = tid; i < D * D; i += 256) { sWa[i] = Wa[i]; sWb[i] = Wb[i]; }
    if (tid < D) { sba[tid] = ba[tid]; sbb[tid] = bb[tid]; }
    __syncthreads();

    int warp = tid >> 5;
    int lane = tid & 31;
    int rowbase = (blockIdx.x * 8 + warp) * 4;
    if (rowbase >= n_rows) return;
    int nr = min(4, n_rows - rowbase);
    int c = lane * 2;

    for (int j = 0; j < nr; j++) {
        float2 v = *reinterpret_cast<const float2*>(
            r + (size_t)(rowbase + j) * D + c);
        *reinterpret_cast<float2*>(&sbuf[warp][j][c]) = v;
    }
    for (int j = nr; j < 4; j++)
        *reinterpret_cast<float2*>(&sbuf[warp][j][c]) = make_float2(0.f, 0.f);
    __syncwarp();

    float2 acc[4];
    {
        float2 bia = *reinterpret_cast<const float2*>(&sba[c]);
        #pragma unroll
        for (int j = 0; j < 4; j++) acc[j] = bia;
        #pragma unroll 8
        for (int k = 0; k < D; k++) {
            float2 w = *reinterpret_cast<const float2*>(&sWa[k * D + c]);
            #pragma unroll
            for (int j = 0; j < 4; j++) {
                float rv = sbuf[warp][j][k];
                acc[j].x = fmaf(rv, w.x, acc[j].x);
                acc[j].y = fmaf(rv, w.y, acc[j].y);
            }
        }
    }
    __syncwarp();
    #pragma unroll
    for (int j = 0; j < 4; j++) {
        sbuf[warp][j][c]     = fmaxf(acc[j].x, 0.f);
        sbuf[warp][j][c + 1] = fmaxf(acc[j].y, 0.f);
    }
    __syncwarp();

    {
        float2 bib = *reinterpret_cast<const float2*>(&sbb[c]);
        #pragma unroll
        for (int j = 0; j < 4; j++) acc[j] = bib;
        #pragma unroll 8
        for (int k = 0; k < D; k++) {
            float2 w = *reinterpret_cast<const float2*>(&sWb[k * D + c]);
            #pragma unroll
            for (int j = 0; j < 4; j++) {
                float rv = sbuf[warp][j][k];
                acc[j].x = fmaf(rv, w.x, acc[j].x);
                acc[j].y = fmaf(rv, w.y, acc[j].y);
            }
        }
    }
    for (int j = 0; j < nr; j++) {
        size_t base = (size_t)(rowbase + j) * D + c;
        *reinterpret_cast<float2*>(out + base) = acc[j];
        *reinterpret_cast<__nv_bfloat162*>(out_bf + base) =
            __float22bfloat162_rn(acc[j]);
    }
}

// ---------------------------------------------------------------------------
// Mean pooling + output head
// ---------------------------------------------------------------------------
__global__ void zero_colsum_kernel(float* p) {
    if (threadIdx.x < D) p[threadIdx.x] = 0.f;
}

__global__ void reduce_cols_kernel(const float* __restrict__ h,
                                   float* __restrict__ colsum, int n_rows) {
    __shared__ float s[256];
    int col = threadIdx.x & 63;
    int rsub = threadIdx.x >> 6;
    float acc = 0.f;
    for (int row = blockIdx.x * 4 + rsub; row < n_rows; row += gridDim.x * 4)
        acc += h[(size_t)row * D + col];
    s[threadIdx.x] = acc;
    __syncthreads();
    if (threadIdx.x < 64) {
        float v = s[threadIdx.x] + s[threadIdx.x + 64] +
                  s[threadIdx.x + 128] + s[threadIdx.x + 192];
        atomicAdd(&colsum[threadIdx.x], v);
    }
}

__global__ void final_out_kernel(const float* __restrict__ colsum,
                                 const float* __restrict__ Wout,
                                 const float* __restrict__ bout,
                                 float* __restrict__ out, int n_rows) {
    int j = threadIdx.x;
    if (j >= 16) return;
    float inv = 1.0f / (float)n_rows;
    float acc = bout[j];
    #pragma unroll
    for (int k = 0; k < D; k++)
        acc = fmaf(colsum[k] * inv, Wout[k * 16 + j], acc);
    out[j] = acc;
}

// ---------------------------------------------------------------------------
// Launch
// ---------------------------------------------------------------------------
extern "C" void kernel_launch(void* const* d_in, const int* in_sizes, int n_in,
                              void* d_out, int out_size) {
    const float* features = (const float*)d_in[0];
    const int*   src      = (const int*)d_in[1];
    const int*   dst      = (const int*)d_in[2];
    const float* Wa[3] = {(const float*)d_in[3], (const float*)d_in[7],  (const float*)d_in[11]};
    const float* ba[3] = {(const float*)d_in[4], (const float*)d_in[8],  (const float*)d_in[12]};
    const float* Wb[3] = {(const float*)d_in[5], (const float*)d_in[9],  (const float*)d_in[13]};
    const float* bb[3] = {(const float*)d_in[6], (const float*)d_in[10], (const float*)d_in[14]};
    const float* Wout = (const float*)d_in[15];
    const float* bout = (const float*)d_in[16];
    float* out = (float*)d_out;

    int n_nodes = in_sizes[0] / D;
    int n_edges = in_sizes[1];

    float *h0, *h1, *aggbuf, *colsum;
    __nv_bfloat16* hb;
    int *deg, *off, *cursor, *srcs;
    cudaGetSymbolAddress((void**)&h0, g_h0);
    cudaGetSymbolAddress((void**)&h1, g_h1);
    cudaGetSymbolAddress((void**)&aggbuf, g_agg);
    cudaGetSymbolAddress((void**)&hb, g_hb);
    cudaGetSymbolAddress((void**)&colsum, g_colsum);
    cudaGetSymbolAddress((void**)&deg, g_deg);
    cudaGetSymbolAddress((void**)&off, g_off);
    cudaGetSymbolAddress((void**)&cursor, g_cursor);
    cudaGetSymbolAddress((void**)&srcs, g_srcs);

    int node_blocks = (n_nodes + 255) / 256;
    int edge_blocks = (n_edges + 255) / 256;
    int gather_blocks = (n_nodes * 8 + 255) / 256;
    int mlp_blocks = (n_nodes + 31) / 32;
    int n2 = n_nodes * D / 2;
    int cvt_blocks = (n2 + 255) / 256;

    // Build CSR (dst -> list of srcs)
    zero_deg_kernel<<<node_blocks, 256>>>(deg, n_nodes);
    hist_kernel<<<edge_blocks, 256>>>(dst, deg, n_edges);
    scan_kernel<<<1, 1024>>>(deg, off, cursor, n_nodes);
    csr_scatter_kernel<<<edge_blocks, 256>>>(src, dst, cursor, srcs, n_edges);

    // bf16 copy of input features
    cvt_bf16_kernel<<<cvt_blocks, 256>>>((const float2*)features,
                                         (__nv_bfloat162*)hb, n2);

    // Layer 0
    gather_kernel<<<gather_blocks, 256>>>(features, hb, aggbuf, off, srcs, n_nodes);
    mlp_kernel<<<mlp_blocks, 256>>>(aggbuf, h0, hb, Wa[0], ba[0], Wb[0], bb[0], n_nodes);
    // Layer 1
    gather_kernel<<<gather_blocks, 256>>>(h0, hb, aggbuf, off, srcs, n_nodes);
    mlp_kernel<<<mlp_blocks, 256>>>(aggbuf, h1, hb, Wa[1], ba[1], Wb[1], bb[1], n_nodes);
    // Layer 2
    gather_kernel<<<gather_blocks, 256>>>(h1, hb, aggbuf, off, srcs, n_nodes);
    mlp_kernel<<<mlp_blocks, 256>>>(aggbuf, h0, hb, Wa[2], ba[2], Wb[2], bb[2], n_nodes);

    // Mean pool + head
    zero_colsum_kernel<<<1, 64>>>(colsum);
    reduce_cols_kernel<<<256, 256>>>(h0, colsum, n_nodes);
    final_out_kernel<<<1, 32>>>(colsum, Wout, bout, out, n_nodes);
}

// round 5
// speedup vs baseline: 1.1866x; 1.0085x over previous
#include <cuda_runtime.h>
#include <cuda_bf16.h>
#include <cstdint>

#define D 64
#define MAX_NODES 50000
#define MAX_EDGES 800000

// Scratch (no allocations allowed)
__device__ __align__(256) float g_h0[MAX_NODES * D];
__device__ __align__(256) float g_h1[MAX_NODES * D];
__device__ __align__(256) float g_agg[MAX_NODES * D];
__device__ __align__(256) __nv_bfloat16 g_hb[MAX_NODES * D];
__device__ __align__(256) float g_colsum[D];
__device__ int g_deg[MAX_NODES];
__device__ int g_off[MAX_NODES + 1];
__device__ int g_cursor[MAX_NODES];
__device__ int g_srcs[MAX_EDGES];   // src ids grouped by dst (CSR)

// ---------------------------------------------------------------------------
// CSR build
// ---------------------------------------------------------------------------
__global__ void zero_deg_kernel(int* deg, int n) {
    int i = blockIdx.x * blockDim.x + threadIdx.x;
    if (i < n) deg[i] = 0;
}

__global__ void hist_kernel(const int* __restrict__ dst, int* __restrict__ deg,
                            int n_edges) {
    int e = blockIdx.x * blockDim.x + threadIdx.x;
    if (e < n_edges) atomicAdd(&deg[dst[e]], 1);
}

__global__ __launch_bounds__(1024)
void scan_kernel(const int* __restrict__ deg, int* __restrict__ off,
                 int* __restrict__ cursor, int n) {
    __shared__ int part[1024];
    int tid = threadIdx.x;
    int chunk = (n + 1023) / 1024;
    int b = tid * chunk;
    int s = 0;
    for (int k = 0; k < chunk; k++) {
        int idx = b + k;
        if (idx < n) s += deg[idx];
    }
    part[tid] = s;
    __syncthreads();
    for (int d = 1; d < 1024; d <<= 1) {
        int v = (tid >= d) ? part[tid - d] : 0;
        __syncthreads();
        part[tid] += v;
        __syncthreads();
    }
    int run = (tid > 0) ? part[tid - 1] : 0;
    for (int k = 0; k < chunk; k++) {
        int idx = b + k;
        if (idx < n) {
            off[idx] = run;
            cursor[idx] = run;
            run += deg[idx];
        }
    }
    if (tid == 1023) off[n] = part[1023];
}

__global__ void csr_scatter_kernel(const int* __restrict__ src,
                                   const int* __restrict__ dst,
                                   int* __restrict__ cursor,
                                   int* __restrict__ srcs, int n_edges) {
    int e = blockIdx.x * blockDim.x + threadIdx.x;
    if (e >= n_edges) return;
    int d = dst[e];
    int pos = atomicAdd(&cursor[d], 1);
    srcs[pos] = src[e];
}

// ---------------------------------------------------------------------------
// features (f32) -> bf16 copy
// ---------------------------------------------------------------------------
__global__ void cvt_bf16_kernel(const float2* __restrict__ in,
                                __nv_bfloat162* __restrict__ out, int n2) {
    int i = blockIdx.x * blockDim.x + threadIdx.x;
    if (i < n2) out[i] = __float22bfloat162_rn(in[i]);
}

// ---------------------------------------------------------------------------
// Gather (warp-per-node): agg[n] = h_f32[n] + sum_{e: dst=n} h_bf16[src[e]]
// Lane covers 2 columns (bf16x2 = 4B). Each neighbor row = one fully
// coalesced 128B warp load. Unroll 8 -> 8 independent row loads in flight.
// ---------------------------------------------------------------------------
__global__ __launch_bounds__(256)
void gather_kernel(const float* __restrict__ hf,
                   const __nv_bfloat16* __restrict__ hb,
                   float* __restrict__ agg,
                   const int* __restrict__ off, const int* __restrict__ srcs,
                   int n_nodes) {
    int gwarp = (blockIdx.x * blockDim.x + threadIdx.x) >> 5;
    int lane = threadIdx.x & 31;
    if (gwarp >= n_nodes) return;
    int node = gwarp;

    float2 acc = *reinterpret_cast<const float2*>(hf + (size_t)node * D + lane * 2);

    int beg = __ldg(off + node);
    int end = __ldg(off + node + 1);

    int i = beg;
    // Full batches of 8 edges
    for (; i + 8 <= end; i += 8) {
        int s[8];
        #pragma unroll
        for (int j = 0; j < 8; j++) s[j] = __ldg(srcs + i + j);
        unsigned u[8];
        #pragma unroll
        for (int j = 0; j < 8; j++)
            u[j] = *reinterpret_cast<const unsigned*>(
                hb + (size_t)s[j] * D + lane * 2);
        #pragma unroll
        for (int j = 0; j < 8; j++) {
            float2 v = __bfloat1622float2(
                *reinterpret_cast<__nv_bfloat162*>(&u[j]));
            acc.x += v.x;
            acc.y += v.y;
        }
    }
    // Tail
    for (; i < end; i++) {
        int s0 = __ldg(srcs + i);
        unsigned u0 = *reinterpret_cast<const unsigned*>(
            hb + (size_t)s0 * D + lane * 2);
        float2 v = __bfloat1622float2(*reinterpret_cast<__nv_bfloat162*>(&u0));
        acc.x += v.x;
        acc.y += v.y;
    }

    *reinterpret_cast<float2*>(agg + (size_t)node * D + lane * 2) = acc;
}

// ---------------------------------------------------------------------------
// Fused MLP: out = relu(r @ Wa + ba) @ Wb + bb ; also emits bf16 copy.
// Block = 256 threads = 8 warps; warp owns 8 rows; lane owns 2 columns.
// Inner loop over k in pairs: float2 broadcast LDS for row data, amortized
// over 8 rows per warp -> FMA-bound, not crossbar-bound.
// ---------------------------------------------------------------------------
__global__ __launch_bounds__(256)
void mlp_kernel(const float* __restrict__ r, float* __restrict__ out,
                __nv_bfloat16* __restrict__ out_bf,
                const float* __restrict__ Wa, const float* __restrict__ ba,
                const float* __restrict__ Wb, const float* __restrict__ bb,
                int n_rows) {
    __shared__ float sWa[D * D];
    __shared__ float sWb[D * D];
    __shared__ float sba[D];
    __shared__ float sbb[D];
    __shared__ float sbuf[8][8][D];   // warp -> 8 rows -> 64 cols

    int tid = threadIdx.x;
    for (int i = tid; i < D * D; i += 256) { sWa[i] = Wa[i]; sWb[i] = Wb[i]; }
    if (tid < D) { sba[tid] = ba[tid]; sbb[tid] = bb[tid]; }
    __syncthreads();

    int warp = tid >> 5;
    int lane = tid & 31;
    int rowbase = (blockIdx.x * 8 + warp) * 8;
    if (rowbase >= n_rows) return;
    int nr = min(8, n_rows - rowbase);
    int c = lane * 2;

    // Stage rows of r into smem (lane: 2 floats per row)
    for (int j = 0; j < nr; j++) {
        float2 v = *reinterpret_cast<const float2*>(
            r + (size_t)(rowbase + j) * D + c);
        *reinterpret_cast<float2*>(&sbuf[warp][j][c]) = v;
    }
    for (int j = nr; j < 8; j++)
        *reinterpret_cast<float2*>(&sbuf[warp][j][c]) = make_float2(0.f, 0.f);
    __syncwarp();

    float2 acc[8];

    // Stage 1: t = relu(r @ Wa + ba)
    {
        float2 bia = *reinterpret_cast<const float2*>(&sba[c]);
        #pragma unroll
        for (int j = 0; j < 8; j++) acc[j] = bia;
        #pragma unroll 8
        for (int kp = 0; kp < D / 2; kp++) {
            float2 w0 = *reinterpret_cast<const float2*>(&sWa[(2 * kp) * D + c]);
            float2 w1 = *reinterpret_cast<const float2*>(&sWa[(2 * kp + 1) * D + c]);
            #pragma unroll
            for (int j = 0; j < 8; j++) {
                float2 rv = *reinterpret_cast<const float2*>(&sbuf[warp][j][2 * kp]);
                acc[j].x = fmaf(rv.x, w0.x, acc[j].x);
                acc[j].y = fmaf(rv.x, w0.y, acc[j].y);
                acc[j].x = fmaf(rv.y, w1.x, acc[j].x);
                acc[j].y = fmaf(rv.y, w1.y, acc[j].y);
            }
        }
    }
    __syncwarp();
    #pragma unroll
    for (int j = 0; j < 8; j++) {
        sbuf[warp][j][c]     = fmaxf(acc[j].x, 0.f);
        sbuf[warp][j][c + 1] = fmaxf(acc[j].y, 0.f);
    }
    __syncwarp();

    // Stage 2: out = t @ Wb + bb
    {
        float2 bib = *reinterpret_cast<const float2*>(&sbb[c]);
        #pragma unroll
        for (int j = 0; j < 8; j++) acc[j] = bib;
        #pragma unroll 8
        for (int kp = 0; kp < D / 2; kp++) {
            float2 w0 = *reinterpret_cast<const float2*>(&sWb[(2 * kp) * D + c]);
            float2 w1 = *reinterpret_cast<const float2*>(&sWb[(2 * kp + 1) * D + c]);
            #pragma unroll
            for (int j = 0; j < 8; j++) {
                float2 rv = *reinterpret_cast<const float2*>(&sbuf[warp][j][2 * kp]);
                acc[j].x = fmaf(rv.x, w0.x, acc[j].x);
                acc[j].y = fmaf(rv.x, w0.y, acc[j].y);
                acc[j].x = fmaf(rv.y, w1.x, acc[j].x);
                acc[j].y = fmaf(rv.y, w1.y, acc[j].y);
            }
        }
    }
    for (int j = 0; j < nr; j++) {
        size_t base = (size_t)(rowbase + j) * D + c;
        *reinterpret_cast<float2*>(out + base) = acc[j];
        *reinterpret_cast<__nv_bfloat162*>(out_bf + base) =
            __float22bfloat162_rn(acc[j]);
    }
}

// ---------------------------------------------------------------------------
// Mean pooling + output head
// ---------------------------------------------------------------------------
__global__ void zero_colsum_kernel(float* p) {
    if (threadIdx.x < D) p[threadIdx.x] = 0.f;
}

__global__ void reduce_cols_kernel(const float* __restrict__ h,
                                   float* __restrict__ colsum, int n_rows) {
    __shared__ float s[256];
    int col = threadIdx.x & 63;
    int rsub = threadIdx.x >> 6;
    float acc = 0.f;
    for (int row = blockIdx.x * 4 + rsub; row < n_rows; row += gridDim.x * 4)
        acc += h[(size_t)row * D + col];
    s[threadIdx.x] = acc;
    __syncthreads();
    if (threadIdx.x < 64) {
        float v = s[threadIdx.x] + s[threadIdx.x + 64] +
                  s[threadIdx.x + 128] + s[threadIdx.x + 192];
        atomicAdd(&colsum[threadIdx.x], v);
    }
}

__global__ void final_out_kernel(const float* __restrict__ colsum,
                                 const float* __restrict__ Wout,
                                 const float* __restrict__ bout,
                                 float* __restrict__ out, int n_rows) {
    int j = threadIdx.x;
    if (j >= 16) return;
    float inv = 1.0f / (float)n_rows;
    float acc = bout[j];
    #pragma unroll
    for (int k = 0; k < D; k++)
        acc = fmaf(colsum[k] * inv, Wout[k * 16 + j], acc);
    out[j] = acc;
}

// ---------------------------------------------------------------------------
// Launch
// ---------------------------------------------------------------------------
extern "C" void kernel_launch(void* const* d_in, const int* in_sizes, int n_in,
                              void* d_out, int out_size) {
    const float* features = (const float*)d_in[0];
    const int*   src      = (const int*)d_in[1];
    const int*   dst      = (const int*)d_in[2];
    const float* Wa[3] = {(const float*)d_in[3], (const float*)d_in[7],  (const float*)d_in[11]};
    const float* ba[3] = {(const float*)d_in[4], (const float*)d_in[8],  (const float*)d_in[12]};
    const float* Wb[3] = {(const float*)d_in[5], (const float*)d_in[9],  (const float*)d_in[13]};
    const float* bb[3] = {(const float*)d_in[6], (const float*)d_in[10], (const float*)d_in[14]};
    const float* Wout = (const float*)d_in[15];
    const float* bout = (const float*)d_in[16];
    float* out = (float*)d_out;

    int n_nodes = in_sizes[0] / D;
    int n_edges = in_sizes[1];

    float *h0, *h1, *aggbuf, *colsum;
    __nv_bfloat16* hb;
    int *deg, *off, *cursor, *srcs;
    cudaGetSymbolAddress((void**)&h0, g_h0);
    cudaGetSymbolAddress((void**)&h1, g_h1);
    cudaGetSymbolAddress((void**)&aggbuf, g_agg);
    cudaGetSymbolAddress((void**)&hb, g_hb);
    cudaGetSymbolAddress((void**)&colsum, g_colsum);
    cudaGetSymbolAddress((void**)&deg, g_deg);
    cudaGetSymbolAddress((void**)&off, g_off);
    cudaGetSymbolAddress((void**)&cursor, g_cursor);
    cudaGetSymbolAddress((void**)&srcs, g_srcs);

    int node_blocks = (n_nodes + 255) / 256;
    int edge_blocks = (n_edges + 255) / 256;
    int gather_blocks = (n_nodes * 32 + 255) / 256;   // warp per node
    int mlp_blocks = (n_nodes + 63) / 64;             // 64 rows per block
    int n2 = n_nodes * D / 2;
    int cvt_blocks = (n2 + 255) / 256;

    // Build CSR (dst -> list of srcs)
    zero_deg_kernel<<<node_blocks, 256>>>(deg, n_nodes);
    hist_kernel<<<edge_blocks, 256>>>(dst, deg, n_edges);
    scan_kernel<<<1, 1024>>>(deg, off, cursor, n_nodes);
    csr_scatter_kernel<<<edge_blocks, 256>>>(src, dst, cursor, srcs, n_edges);

    // bf16 copy of input features
    cvt_bf16_kernel<<<cvt_blocks, 256>>>((const float2*)features,
                                         (__nv_bfloat162*)hb, n2);

    // Layer 0
    gather_kernel<<<gather_blocks, 256>>>(features, hb, aggbuf, off, srcs, n_nodes);
    mlp_kernel<<<mlp_blocks, 256>>>(aggbuf, h0, hb, Wa[0], ba[0], Wb[0], bb[0], n_nodes);
    // Layer 1
    gather_kernel<<<gather_blocks, 256>>>(h0, hb, aggbuf, off, srcs, n_nodes);
    mlp_kernel<<<mlp_blocks, 256>>>(aggbuf, h1, hb, Wa[1], ba[1], Wb[1], bb[1], n_nodes);
    // Layer 2
    gather_kernel<<<gather_blocks, 256>>>(h1, hb, aggbuf, off, srcs, n_nodes);
    mlp_kernel<<<mlp_blocks, 256>>>(aggbuf, h0, hb, Wa[2], ba[2], Wb[2], bb[2], n_nodes);

    // Mean pool + head
    zero_colsum_kernel<<<1, 64>>>(colsum);
    reduce_cols_kernel<<<256, 256>>>(h0, colsum, n_nodes);
    final_out_kernel<<<1, 32>>>(colsum, Wout, bout, out, n_nodes);
}